// round 15
// baseline (speedup 1.0000x reference)
#include <cuda_runtime.h>
#include <cuda_bf16.h>
#include <cstdint>

// MvCnnDownLayer via mma.sync bf16 2-split (3 products, fp32 accum).
// 8-CTA clusters, oc-quarter warps, W fragments hoisted, depth-2 prefetch,
// SPLIT cluster barrier: wait hidden under halo-free k-tiles.
//   out[b,h] = relu(conv1dW(in[b,h] + out[b,h-1]) + bias)
// B=16,H=256,W=256,C=32,K=5. Grid 128 = 16 clusters x 8 CTAs, 256 thr.
// Per row: conv(6 halo-free kt) -> cluster.wait -> conv(4 halo-dep kt) ->
// epilogue(state+halo push) -> cluster.arrive -> STG -> __syncthreads.
// tile0: dep kt 0-3 (reads ax 0,1); tile1: dep kt 6-9 (reads ax 34,35).

#define Bn 16
#define Hn 256
#define Wn 256
#define Cn 32
#define NT 256

#define ROWB 80u                    // bytes per A/W SMEM row (32 bf16 + pad)
#define APAR (36u * ROWB)           // 2880 per parity per plane
#define OFF_AH 0u
#define OFF_AL 5760u
#define OFF_WH 11520u               // 160 rows x 80B
#define OFF_WL 24320u
#define SMEM_BYTES 37120u

__device__ __forceinline__ void ldm4(uint32_t a, uint32_t r[4]) {
    asm volatile("ldmatrix.sync.aligned.m8n8.x4.shared.b16 {%0,%1,%2,%3}, [%4];"
                 : "=r"(r[0]), "=r"(r[1]), "=r"(r[2]), "=r"(r[3]) : "r"(a));
}
__device__ __forceinline__ void ldm2t(uint32_t a, uint32_t r[2]) {
    asm volatile("ldmatrix.sync.aligned.m8n8.x2.trans.shared.b16 {%0,%1}, [%2];"
                 : "=r"(r[0]), "=r"(r[1]) : "r"(a));
}
__device__ __forceinline__ void mma16816(float d[4], const uint32_t a[4],
                                         uint32_t b0, uint32_t b1) {
    asm volatile("mma.sync.aligned.m16n8k16.row.col.f32.bf16.bf16.f32 "
                 "{%0,%1,%2,%3}, {%4,%5,%6,%7}, {%8,%9}, {%0,%1,%2,%3};"
                 : "+f"(d[0]), "+f"(d[1]), "+f"(d[2]), "+f"(d[3])
                 : "r"(a[0]), "r"(a[1]), "r"(a[2]), "r"(a[3]), "r"(b0), "r"(b1));
}
__device__ __forceinline__ uint32_t pack2(float lo, float hi) {
    uint32_t r;
    asm("cvt.rn.satfinite.bf16x2.f32 %0, %1, %2;" : "=r"(r) : "f"(hi), "f"(lo));
    return r;
}
__device__ __forceinline__ float bf16rt(float x) {
    return __bfloat162float(__float2bfloat16(x));
}

__global__ void __cluster_dims__(8, 1, 1) __launch_bounds__(NT, 1)
mvcnn_mma8_kernel(const float* __restrict__ in, const float* __restrict__ wg,
                  const float* __restrict__ bias, float* __restrict__ out)
{
    extern __shared__ char smb[];
    const uint32_t smem = (uint32_t)__cvta_generic_to_shared(smb);

    const int tid  = threadIdx.x;
    const int lane = tid & 31;
    const int wid  = tid >> 5;          // 0..7
    const int tile = wid & 1;           // m16-tile within 32-x segment
    const int ocq4 = wid >> 1;          // oc quarter 0..3
    const int b    = blockIdx.x >> 3;
    const int rank = blockIdx.x & 7;
    const int seg  = rank * 32;

    const int q   = lane & 3;
    const int xr  = lane >> 2;
    const int ocq = ocq4 * 8 + q * 2;   // this thread's oc pair
    const int xl0 = tile * 16 + xr;     // local x; this thread: xl0, xl0+8

    // halo-free kt range: tile0 -> kt 4..9, tile1 -> kt 0..5
    // halo-dep  kt range: tile0 -> kt 0..3, tile1 -> kt 6..9
    const int ktFree = tile ? 0 : 4;    // 6 kts from here
    const int ktDep  = tile ? 6 : 0;    // 4 kts from here

    // --- stage weights: row = k*32+c, col = oc; bf16 hi/lo planes ---
    for (int idx = tid; idx < 5 * Cn * Cn; idx += NT) {
        int oc = idx & 31, ck = idx >> 5, k = ck % 5, c = ck / 5;
        float w  = wg[idx];
        float hf = bf16rt(w);
        uint32_t off = (uint32_t)(k * 32 + c) * ROWB + (uint32_t)oc * 2u;
        *(__nv_bfloat16*)(smb + OFF_WH + off) = __float2bfloat16(hf);
        *(__nv_bfloat16*)(smb + OFF_WL + off) = __float2bfloat16(w - hf);
    }

    const size_t bHW = (size_t)b * Hn * Wn;

    // --- halo rows ax in {0,1,34,35}: interior -> load row 0 (parity 0);
    //     edge-of-image -> zero BOTH parities (never rewritten) ---
    if (tid < 128) {
        int par  = tid >> 6;            // 0,1
        int side = (tid >> 5) & 1;      // 0=left, 1=right
        int rr   = (tid >> 4) & 1;      // row within side
        int cp   = tid & 15;            // channel pair
        uint32_t ax = side ? (uint32_t)(34 + rr) : (uint32_t)rr;
        int gx = seg + (side ? 32 + rr : rr - 2);
        bool valid = (gx >= 0) && (gx < Wn);
        uint32_t off = (uint32_t)par * APAR + ax * ROWB + (uint32_t)cp * 4u;
        if (!valid) {
            *(uint32_t*)(smb + OFF_AH + off) = 0u;
            *(uint32_t*)(smb + OFF_AL + off) = 0u;
        } else if (par == 0) {
            float2 v = *(const float2*)(in + (bHW + gx) * Cn + cp * 2);
            float h0 = bf16rt(v.x), h1 = bf16rt(v.y);
            *(uint32_t*)(smb + OFF_AH + off) = pack2(h0, h1);
            *(uint32_t*)(smb + OFF_AL + off) = pack2(v.x - h0, v.y - h1);
        }
    }

    // --- bias for this thread's 2 channels ---
    float2 bvt = *(const float2*)(bias + ocq);
    const float bv0 = bvt.x, bv1 = bvt.y;

    const uint32_t frag_base = (uint32_t)(lane & 15) * ROWB + (uint32_t)(lane >> 4) * 16u;

    // --- row-0 interior state = in[0] ---
#pragma unroll
    for (int s = 0; s < 2; ++s) {
        int lx = xl0 + s * 8;
        const float* ip = in + (bHW + (seg + lx)) * Cn + ocq;
        float2 v = *(const float2*)ip;
        float h0 = bf16rt(v.x), h1 = bf16rt(v.y);
        uint32_t off = (uint32_t)(lx + 2) * ROWB + (uint32_t)ocq * 2u;
        *(uint32_t*)(smb + OFF_AH + off) = pack2(h0, h1);
        *(uint32_t*)(smb + OFF_AL + off) = pack2(v.x - h0, v.y - h1);
    }
    __syncthreads();

    // --- remote SMEM bases of neighbor CTAs ---
    uint32_t rbaseL = 0, rbaseR = 0;
    if (rank > 0)
        asm("mapa.shared::cluster.u32 %0, %1, %2;" : "=r"(rbaseL) : "r"(smem), "r"(rank - 1));
    if (rank < 7)
        asm("mapa.shared::cluster.u32 %0, %1, %2;" : "=r"(rbaseR) : "r"(smem), "r"(rank + 1));

    // --- hoist Wh + Wl fragments (row-invariant): 10 kt x 2 regs each ---
    const uint32_t wHb = smem + OFF_WH + frag_base + (uint32_t)ocq4 * 16u;
    const uint32_t wLb = smem + OFF_WL + frag_base + (uint32_t)ocq4 * 16u;
    uint32_t whf[10][2], wlf[10][2];
#pragma unroll
    for (int kt = 0; kt < 10; ++kt) {
        ldm2t(wHb + (uint32_t)kt * (16u * ROWB), whf[kt]);
        ldm2t(wLb + (uint32_t)kt * (16u * ROWB), wlf[kt]);
    }

    // --- depth-2 prefetch pipeline: cur = in[i+1] (in regs) ---
    float2 cur[2];
#pragma unroll
    for (int s = 0; s < 2; ++s)
        cur[s] = *(const float2*)(in + (bHW + (size_t)1 * Wn + (seg + xl0 + s * 8)) * Cn + ocq);

    for (int i = 0; i < Hn; ++i) {
        const int  p    = i & 1;
        const bool more = (i + 1 < Hn);

        // issue prefetch for in[i+2] (consumed next row)
        float2 nxt[2];
        if (i + 2 < Hn) {
#pragma unroll
            for (int s = 0; s < 2; ++s)
                nxt[s] = *(const float2*)(in + (bHW + (size_t)(i + 2) * Wn
                                                + (seg + xl0 + s * 8)) * Cn + ocq);
        }

        float dHH[4], dHL[4], dLH[4];
#pragma unroll
        for (int e = 0; e < 4; ++e) { dHH[e] = 0.f; dHL[e] = 0.f; dLH[e] = 0.f; }

        const uint32_t aH = smem + OFF_AH + (uint32_t)p * APAR + frag_base;
        const uint32_t aL = smem + OFF_AL + (uint32_t)p * APAR + frag_base;

        // --- phase 1: 6 halo-free k-tiles (local rows only) ---
#pragma unroll
        for (int j = 0; j < 6; ++j) {
            const int kt = ktFree + j;
            const int k = kt >> 1, ch = kt & 1;
            const uint32_t aoff = (uint32_t)(tile * 16 + k) * ROWB + (uint32_t)ch * 32u;
            uint32_t ah[4], al[4];
            ldm4(aH + aoff, ah);
            ldm4(aL + aoff, al);
            mma16816(dHH, ah, whf[kt][0], whf[kt][1]);
            mma16816(dHL, ah, wlf[kt][0], wlf[kt][1]);
            mma16816(dLH, al, whf[kt][0], whf[kt][1]);
        }

        // --- cluster wait (acquire): neighbor halo of THIS row now visible.
        //     Hidden under the phase-1 MMA stream still draining. ---
        if (i > 0)
            asm volatile("barrier.cluster.wait.aligned;" ::: "memory");

        // --- phase 2: 4 halo-dependent k-tiles ---
#pragma unroll
        for (int j = 0; j < 4; ++j) {
            const int kt = ktDep + j;
            const int k = kt >> 1, ch = kt & 1;
            const uint32_t aoff = (uint32_t)(tile * 16 + k) * ROWB + (uint32_t)ch * 32u;
            uint32_t ah[4], al[4];
            ldm4(aH + aoff, ah);
            ldm4(aL + aoff, al);
            mma16816(dHH, ah, whf[kt][0], whf[kt][1]);
            mma16816(dHL, ah, wlf[kt][0], wlf[kt][1]);
            mma16816(dLH, al, whf[kt][0], whf[kt][1]);
        }

        // --- epilogue: state build + halo push FIRST, then arrive, then STG ---
        float v0s[2], v1s[2];
        const uint32_t wAH = OFF_AH + (uint32_t)(p ^ 1) * APAR;
        const uint32_t wAL = OFF_AL + (uint32_t)(p ^ 1) * APAR;
#pragma unroll
        for (int s = 0; s < 2; ++s) {
            const int lx = xl0 + s * 8;
            float v0 = fmaxf(dHH[2 * s + 0] + dHL[2 * s + 0] + dLH[2 * s + 0] + bv0, 0.f);
            float v1 = fmaxf(dHH[2 * s + 1] + dHL[2 * s + 1] + dLH[2 * s + 1] + bv1, 0.f);
            v0s[s] = v0; v1s[s] = v1;
            if (more) {
                float xn0 = v0 + cur[s].x;
                float xn1 = v1 + cur[s].y;
                float h0 = bf16rt(xn0), h1 = bf16rt(xn1);
                uint32_t ph = pack2(h0, h1);
                uint32_t pl = pack2(xn0 - h0, xn1 - h1);
                uint32_t off = (uint32_t)(lx + 2) * ROWB + (uint32_t)ocq * 2u;
                *(uint32_t*)(smb + wAH + off) = ph;
                *(uint32_t*)(smb + wAL + off) = pl;
                if (lx < 2 && rank > 0) {       // -> left neighbor ax 34,35
                    uint32_t roff = (uint32_t)(34 + lx) * ROWB + (uint32_t)ocq * 2u;
                    asm volatile("st.shared::cluster.b32 [%0], %1;"
                                 :: "r"(rbaseL + wAH + roff), "r"(ph) : "memory");
                    asm volatile("st.shared::cluster.b32 [%0], %1;"
                                 :: "r"(rbaseL + wAL + roff), "r"(pl) : "memory");
                }
                if (lx >= 30 && rank < 7) {     // -> right neighbor ax 0,1
                    uint32_t roff = (uint32_t)(lx - 30) * ROWB + (uint32_t)ocq * 2u;
                    asm volatile("st.shared::cluster.b32 [%0], %1;"
                                 :: "r"(rbaseR + wAH + roff), "r"(ph) : "memory");
                    asm volatile("st.shared::cluster.b32 [%0], %1;"
                                 :: "r"(rbaseR + wAL + roff), "r"(pl) : "memory");
                }
            }
        }

        // arrive (release): publishes local state + remote halo stores.
        if (more)
            asm volatile("barrier.cluster.arrive.aligned;" ::: "memory");

        // output store + prefetch rotate (off the inter-CTA critical path)
        float* op = out + (bHW + (size_t)i * Wn) * Cn;
#pragma unroll
        for (int s = 0; s < 2; ++s)
            *(float2*)(op + (size_t)(seg + xl0 + s * 8) * Cn + ocq)
                = make_float2(v0s[s], v1s[s]);
        cur[0] = nxt[0]; cur[1] = nxt[1];

        // CTA-local ordering of Xs[p^1] writes for next row's phase-1 reads
        if (more)
            __syncthreads();
    }
}

extern "C" void kernel_launch(void* const* d_in, const int* in_sizes, int n_in,
                              void* d_out, int out_size)
{
    const float* in   = (const float*)d_in[0];
    const float* w    = (const float*)d_in[1];
    const float* bias = (const float*)d_in[2];
    float* out        = (float*)d_out;
    (void)in_sizes; (void)n_in; (void)out_size;

    cudaFuncSetAttribute(mvcnn_mma8_kernel,
                         cudaFuncAttributeMaxDynamicSharedMemorySize, SMEM_BYTES);
    mvcnn_mma8_kernel<<<dim3(Bn * 8), dim3(NT), SMEM_BYTES>>>(in, w, bias, out);
}